// round 3
// baseline (speedup 1.0000x reference)
#include <cuda_runtime.h>
#include <cuda_bf16.h>

// Problem constants (fixed by setup_inputs)
#define IH 2160
#define IW 3840
#define HW (IH * IW)
#define KS 25
#define PADK 12
#define LH (IH + 22)
#define LW (IW + 22)
#define L3 (3 * LH * LW)

// Blur tiling
#define TILE 32
#define SROWS 56          // 32 + 24 halo
#define SCOLS 56
#define SSTRIDE 57        // odd stride -> conflict-free LDS
#define BLK_THREADS 128   // 4 warps: warp w handles x-group w (8 outputs wide), lane = y row

// Laplacian reduction scratch
#define LAP_THREADS 256
#define LAP_BLOCKS ((L3 + LAP_THREADS - 1) / LAP_THREADS)   // 98753
__device__ float g_partials[LAP_BLOCKS];

__device__ __forceinline__ int clampi(int v, int lo, int hi) {
    return min(max(v, lo), hi);
}

// ---------------------------------------------------------------------------
// Kernel 1: 25x25 depthwise blur with edge-replicate pad, + noise.
// Channels 0,1 packed as f32x2 (FFMA2 full-rate path), channel 2 scalar.
// ---------------------------------------------------------------------------
__global__ void __launch_bounds__(BLK_THREADS)
blur_kernel(const float* __restrict__ img,
            const float* __restrict__ noise,
            const float* __restrict__ g,
            float* __restrict__ out)
{
    __shared__ float2 spk[SROWS * SSTRIDE];  // channels 0,1 packed
    __shared__ float  s2 [SROWS * SSTRIDE];  // channel 2
    __shared__ float  swt[KS * KS];

    const int tx0 = blockIdx.x * TILE;
    const int ty0 = blockIdx.y * TILE;
    const int tid = threadIdx.x;

    // load 25x25 weights
    for (int i = tid; i < KS * KS; i += BLK_THREADS) swt[i] = g[i];

    // load input tile with edge clamp (3 channels)
    for (int i = tid; i < SROWS * SCOLS; i += BLK_THREADS) {
        int r = i / SCOLS, c = i % SCOLS;
        int gy = clampi(ty0 - PADK + r, 0, IH - 1);
        int gx = clampi(tx0 - PADK + c, 0, IW - 1);
        int gi = gy * IW + gx;
        spk[r * SSTRIDE + c] = make_float2(img[gi], img[HW + gi]);
        s2 [r * SSTRIDE + c] = img[2 * HW + gi];
    }
    __syncthreads();

    const int lane = tid & 31;      // output row within tile
    const int wid  = tid >> 5;      // x-group (0..3)
    const int xb   = wid * 8;       // column base within tile

    unsigned long long acc01[8];
    float acc2[8];
#pragma unroll
    for (int j = 0; j < 8; j++) { acc01[j] = 0ull; acc2[j] = 0.0f; }

    for (int ky = 0; ky < KS; ++ky) {
        const unsigned long long* rowp =
            reinterpret_cast<const unsigned long long*>(spk + (lane + ky) * SSTRIDE + xb);
        const float* row2 = s2 + (lane + ky) * SSTRIDE + xb;
        const float* wrow = swt + ky * KS;

        // prime 8-wide sliding windows (cols xb+0 .. xb+7)
        unsigned long long w01[8];
        float w2[8];
#pragma unroll
        for (int j = 0; j < 8; j++) { w01[j] = rowp[j]; w2[j] = row2[j]; }

#pragma unroll
        for (int kx = 0; kx < KS; ++kx) {
            float wv = wrow[kx];                       // uniform LDS broadcast
            unsigned long long ww;
            asm("mov.b64 %0, {%1, %1};" : "=l"(ww) : "r"(__float_as_uint(wv)));
#pragma unroll
            for (int j = 0; j < 8; j++) {
                asm("fma.rn.f32x2 %0, %1, %2, %0;"
                    : "+l"(acc01[j]) : "l"(w01[j]), "l"(ww));
                acc2[j] = fmaf(w2[j], wv, acc2[j]);
            }
            if (kx < KS - 1) {
#pragma unroll
                for (int j = 0; j < 7; j++) { w01[j] = w01[j + 1]; w2[j] = w2[j + 1]; }
                w01[7] = rowp[8 + kx];
                w2 [7] = row2[8 + kx];
            }
        }
    }

    const int y = ty0 + lane;
    if (y < IH) {
        const int x = tx0 + xb;
        const int base = y * IW + x;
        float4 n0 = *reinterpret_cast<const float4*>(noise + base);
        float4 n1 = *reinterpret_cast<const float4*>(noise + base + 4);

        float c0[8], c1[8];
#pragma unroll
        for (int j = 0; j < 8; j++) {
            float2 f = *reinterpret_cast<float2*>(&acc01[j]);
            c0[j] = f.x; c1[j] = f.y;
        }
        *reinterpret_cast<float4*>(out + 0 * HW + base) =
            make_float4(c0[0] + n0.x, c0[1] + n0.y, c0[2] + n0.z, c0[3] + n0.w);
        *reinterpret_cast<float4*>(out + 0 * HW + base + 4) =
            make_float4(c0[4] + n1.x, c0[5] + n1.y, c0[6] + n1.z, c0[7] + n1.w);
        *reinterpret_cast<float4*>(out + 1 * HW + base) =
            make_float4(c1[0] + n0.x, c1[1] + n0.y, c1[2] + n0.z, c1[3] + n0.w);
        *reinterpret_cast<float4*>(out + 1 * HW + base + 4) =
            make_float4(c1[4] + n1.x, c1[5] + n1.y, c1[6] + n1.z, c1[7] + n1.w);
        *reinterpret_cast<float4*>(out + 2 * HW + base) =
            make_float4(acc2[0] + n0.x, acc2[1] + n0.y, acc2[2] + n0.z, acc2[3] + n0.w);
        *reinterpret_cast<float4*>(out + 2 * HW + base + 4) =
            make_float4(acc2[4] + n1.x, acc2[5] + n1.y, acc2[6] + n1.z, acc2[7] + n1.w);
    }
}

// ---------------------------------------------------------------------------
// Kernel 2: Laplacian (3x3, pad=12 replicate -> output LH x LW per channel),
// squared, summed per block into g_partials (deterministic tree reduce).
// ---------------------------------------------------------------------------
__global__ void __launch_bounds__(LAP_THREADS)
lap_kernel(const float* __restrict__ img)
{
    int idx = blockIdx.x * LAP_THREADS + threadIdx.x;
    float v = 0.0f;
    if (idx < L3) {
        int c  = idx / (LH * LW);
        int r  = idx - c * (LH * LW);
        int oy = r / LW;
        int ox = r - oy * LW;
        const float* p = img + c * HW;

        int ru = clampi(oy - 12, 0, IH - 1);
        int rc = clampi(oy - 11, 0, IH - 1);
        int rd = clampi(oy - 10, 0, IH - 1);
        int cl = clampi(ox - 12, 0, IW - 1);
        int cc = clampi(ox - 11, 0, IW - 1);
        int cr = clampi(ox - 10, 0, IW - 1);

        float val = 4.0f * p[rc * IW + cc]
                  - p[ru * IW + cc] - p[rd * IW + cc]
                  - p[rc * IW + cl] - p[rc * IW + cr];
        v = val * val;
    }
    __shared__ float sbuf[LAP_THREADS];
    sbuf[threadIdx.x] = v;
    __syncthreads();
#pragma unroll
    for (int s = LAP_THREADS / 2; s > 0; s >>= 1) {
        if (threadIdx.x < s) sbuf[threadIdx.x] += sbuf[threadIdx.x + s];
        __syncthreads();
    }
    if (threadIdx.x == 0) g_partials[blockIdx.x] = sbuf[0];
}

// ---------------------------------------------------------------------------
// Kernel 3: final deterministic reduction in double -> mean scalar.
// ---------------------------------------------------------------------------
__global__ void __launch_bounds__(256)
reduce_kernel(float* __restrict__ out_scalar)
{
    __shared__ double sd[256];
    double s = 0.0;
    for (int i = threadIdx.x; i < LAP_BLOCKS; i += 256) s += (double)g_partials[i];
    sd[threadIdx.x] = s;
    __syncthreads();
#pragma unroll
    for (int k = 128; k > 0; k >>= 1) {
        if (threadIdx.x < k) sd[threadIdx.x] += sd[threadIdx.x + k];
        __syncthreads();
    }
    if (threadIdx.x == 0)
        out_scalar[0] = (float)(sd[0] / (double)L3);
}

extern "C" void kernel_launch(void* const* d_in, const int* in_sizes, int n_in,
                              void* d_out, int out_size)
{
    const float* img   = (const float*)d_in[0];  // (1,3,2160,3840)
    const float* noise = (const float*)d_in[1];  // (1,1,2160,3840)
    const float* g     = (const float*)d_in[2];  // (25,25)
    float* out = (float*)d_out;                  // [3*H*W conv output, 1 scalar]

    dim3 gridB(IW / TILE, (IH + TILE - 1) / TILE);   // 120 x 68
    blur_kernel<<<gridB, BLK_THREADS>>>(img, noise, g, out);

    lap_kernel<<<LAP_BLOCKS, LAP_THREADS>>>(img);
    reduce_kernel<<<1, 256>>>(out + (out_size - 1));
}

// round 4
// speedup vs baseline: 1.1620x; 1.1620x over previous
#include <cuda_runtime.h>
#include <cuda_bf16.h>

// Problem constants (fixed by setup_inputs)
#define IH 2160
#define IW 3840
#define HW (IH * IW)
#define KS 25
#define PADK 12
#define LH (IH + 22)
#define LW (IW + 22)
#define L3 (3 * LH * LW)

// Blur tiling
#define TILE 32
#define SROWS 56          // 32 + 24 halo
#define SCOLS 56
#define SSTRIDE 57        // odd stride -> conflict-free LDS
#define BLK_THREADS 128   // 4 warps: warp w = x-group (8 outputs wide), lane = y row

// Laplacian: one block per output row (channel, oy)
#define LAP_ROWS (3 * LH)            // 6546
#define LAP_THREADS 256
__device__ float g_partials[LAP_ROWS];

__device__ __forceinline__ int clampi(int v, int lo, int hi) {
    return min(max(v, lo), hi);
}

// ---------------------------------------------------------------------------
// Kernel 1: 25x25 depthwise blur with edge-replicate pad, + noise.
// Channels 0,1 packed as f32x2 (FFMA2 full-rate path), channel 2 scalar.
// Weight row preloaded into registers -> batched LDS, no per-kx serial stall.
// ---------------------------------------------------------------------------
__global__ void __launch_bounds__(BLK_THREADS, 5)
blur_kernel(const float* __restrict__ img,
            const float* __restrict__ noise,
            const float* __restrict__ g,
            float* __restrict__ out)
{
    __shared__ float2 spk[SROWS * SSTRIDE];  // channels 0,1 packed
    __shared__ float  s2 [SROWS * SSTRIDE];  // channel 2
    __shared__ float  swt[KS * KS];

    const int tx0 = blockIdx.x * TILE;
    const int ty0 = blockIdx.y * TILE;
    const int tid = threadIdx.x;

    // load 25x25 weights
    for (int i = tid; i < KS * KS; i += BLK_THREADS) swt[i] = g[i];

    // load input tile with edge clamp (3 channels)
    for (int i = tid; i < SROWS * SCOLS; i += BLK_THREADS) {
        int r = i / SCOLS, c = i % SCOLS;
        int gy = clampi(ty0 - PADK + r, 0, IH - 1);
        int gx = clampi(tx0 - PADK + c, 0, IW - 1);
        int gi = gy * IW + gx;
        spk[r * SSTRIDE + c] = make_float2(img[gi], img[HW + gi]);
        s2 [r * SSTRIDE + c] = img[2 * HW + gi];
    }
    __syncthreads();

    const int lane = tid & 31;      // output row within tile
    const int wid  = tid >> 5;      // x-group (0..3)
    const int xb   = wid * 8;       // column base within tile

    unsigned long long acc01[8];
    float acc2[8];
#pragma unroll
    for (int j = 0; j < 8; j++) { acc01[j] = 0ull; acc2[j] = 0.0f; }

#pragma unroll 1
    for (int ky = 0; ky < KS; ++ky) {
        const unsigned long long* rowp =
            reinterpret_cast<const unsigned long long*>(spk + (lane + ky) * SSTRIDE + xb);
        const float* row2 = s2 + (lane + ky) * SSTRIDE + xb;
        const float* wrow = swt + ky * KS;

        // preload the whole weight row into registers (batched LDS, MLP=25)
        float wreg[KS];
#pragma unroll
        for (int i = 0; i < KS; i++) wreg[i] = wrow[i];

        // prime 8-wide sliding windows (cols xb+0 .. xb+7)
        unsigned long long w01[8];
        float w2[8];
#pragma unroll
        for (int j = 0; j < 8; j++) { w01[j] = rowp[j]; w2[j] = row2[j]; }

#pragma unroll
        for (int kx = 0; kx < KS; ++kx) {
            float wv = wreg[kx];
            // channel-2 scalar FMAs first (no pack dependency)
#pragma unroll
            for (int j = 0; j < 8; j++)
                acc2[j] = fmaf(w2[j], wv, acc2[j]);
            unsigned long long ww;
            asm("mov.b64 %0, {%1, %1};" : "=l"(ww) : "r"(__float_as_uint(wv)));
#pragma unroll
            for (int j = 0; j < 8; j++)
                asm("fma.rn.f32x2 %0, %1, %2, %0;"
                    : "+l"(acc01[j]) : "l"(w01[j]), "l"(ww));
            if (kx < KS - 1) {
#pragma unroll
                for (int j = 0; j < 7; j++) { w01[j] = w01[j + 1]; w2[j] = w2[j + 1]; }
                w01[7] = rowp[8 + kx];
                w2 [7] = row2[8 + kx];
            }
        }
    }

    const int y = ty0 + lane;
    if (y < IH) {
        const int x = tx0 + xb;
        const int base = y * IW + x;
        float4 n0 = *reinterpret_cast<const float4*>(noise + base);
        float4 n1 = *reinterpret_cast<const float4*>(noise + base + 4);

        float c0[8], c1[8];
#pragma unroll
        for (int j = 0; j < 8; j++) {
            float2 f = *reinterpret_cast<float2*>(&acc01[j]);
            c0[j] = f.x; c1[j] = f.y;
        }
        *reinterpret_cast<float4*>(out + 0 * HW + base) =
            make_float4(c0[0] + n0.x, c0[1] + n0.y, c0[2] + n0.z, c0[3] + n0.w);
        *reinterpret_cast<float4*>(out + 0 * HW + base + 4) =
            make_float4(c0[4] + n1.x, c0[5] + n1.y, c0[6] + n1.z, c0[7] + n1.w);
        *reinterpret_cast<float4*>(out + 1 * HW + base) =
            make_float4(c1[0] + n0.x, c1[1] + n0.y, c1[2] + n0.z, c1[3] + n0.w);
        *reinterpret_cast<float4*>(out + 1 * HW + base + 4) =
            make_float4(c1[4] + n1.x, c1[5] + n1.y, c1[6] + n1.z, c1[7] + n1.w);
        *reinterpret_cast<float4*>(out + 2 * HW + base) =
            make_float4(acc2[0] + n0.x, acc2[1] + n0.y, acc2[2] + n0.z, acc2[3] + n0.w);
        *reinterpret_cast<float4*>(out + 2 * HW + base + 4) =
            make_float4(acc2[4] + n1.x, acc2[5] + n1.y, acc2[6] + n1.z, acc2[7] + n1.w);
    }
}

// ---------------------------------------------------------------------------
// Kernel 2: Laplacian (3x3, pad=12 replicate -> LH x LW per channel), squared,
// one block per output row, row clamps hoisted, no divides in inner loop.
// ---------------------------------------------------------------------------
__global__ void __launch_bounds__(LAP_THREADS)
lap_kernel(const float* __restrict__ img)
{
    const int row = blockIdx.x;          // 0 .. LAP_ROWS-1
    const int c   = row / LH;            // uniform per block (one divide total)
    const int oy  = row - c * LH;
    const float* p = img + c * HW;

    const int ru = clampi(oy - 12, 0, IH - 1);
    const int rc = clampi(oy - 11, 0, IH - 1);
    const int rd = clampi(oy - 10, 0, IH - 1);
    const float* __restrict__ pu = p + ru * IW;
    const float* __restrict__ pc = p + rc * IW;
    const float* __restrict__ pd = p + rd * IW;

    float acc = 0.0f;
    for (int ox = threadIdx.x; ox < LW; ox += LAP_THREADS) {
        int cl = clampi(ox - 12, 0, IW - 1);
        int cc = clampi(ox - 11, 0, IW - 1);
        int cr = clampi(ox - 10, 0, IW - 1);
        float v = 4.0f * pc[cc] - pu[cc] - pd[cc] - pc[cl] - pc[cr];
        acc = fmaf(v, v, acc);
    }

    __shared__ float sbuf[LAP_THREADS];
    sbuf[threadIdx.x] = acc;
    __syncthreads();
#pragma unroll
    for (int s = LAP_THREADS / 2; s > 0; s >>= 1) {
        if (threadIdx.x < s) sbuf[threadIdx.x] += sbuf[threadIdx.x + s];
        __syncthreads();
    }
    if (threadIdx.x == 0) g_partials[row] = sbuf[0];
}

// ---------------------------------------------------------------------------
// Kernel 3: final deterministic reduction in double -> mean scalar.
// ---------------------------------------------------------------------------
__global__ void __launch_bounds__(256)
reduce_kernel(float* __restrict__ out_scalar)
{
    __shared__ double sd[256];
    double s = 0.0;
    for (int i = threadIdx.x; i < LAP_ROWS; i += 256) s += (double)g_partials[i];
    sd[threadIdx.x] = s;
    __syncthreads();
#pragma unroll
    for (int k = 128; k > 0; k >>= 1) {
        if (threadIdx.x < k) sd[threadIdx.x] += sd[threadIdx.x + k];
        __syncthreads();
    }
    if (threadIdx.x == 0)
        out_scalar[0] = (float)(sd[0] / (double)L3);
}

extern "C" void kernel_launch(void* const* d_in, const int* in_sizes, int n_in,
                              void* d_out, int out_size)
{
    const float* img   = (const float*)d_in[0];  // (1,3,2160,3840)
    const float* noise = (const float*)d_in[1];  // (1,1,2160,3840)
    const float* g     = (const float*)d_in[2];  // (25,25)
    float* out = (float*)d_out;                  // [3*H*W conv output, 1 scalar]

    dim3 gridB(IW / TILE, (IH + TILE - 1) / TILE);   // 120 x 68
    blur_kernel<<<gridB, BLK_THREADS>>>(img, noise, g, out);

    lap_kernel<<<LAP_ROWS, LAP_THREADS>>>(img);
    reduce_kernel<<<1, 256>>>(out + (out_size - 1));
}

// round 5
// speedup vs baseline: 1.2280x; 1.0569x over previous
#include <cuda_runtime.h>
#include <cuda_bf16.h>

typedef unsigned long long ULL;

// Problem constants (fixed by setup_inputs)
#define IH 2160
#define IW 3840
#define HW (IH * IW)
#define KS 25
#define PADK 12
#define LH (IH + 22)
#define LW (IW + 22)
#define L3 (3 * LH * LW)

// Blur tiling: 32 cols x 64 rows per block; thread handles rows (lane, lane+32)
#define TILE_X 32
#define TILE_Y 64
#define SROWS 88           // 64 + 24 halo
#define SCOLS 56           // 32 + 24 halo
#define SSTRIDE 57
#define S2PROWS 56         // pair rows: r pairs (r, r+32)
#define BLK_THREADS 128    // 4 warps x 8 cols, lane = row index

#define SPK_ELEMS (SROWS * SSTRIDE)            // float2
#define S2P_ELEMS (S2PROWS * SSTRIDE)          // float2
#define SWT_ELEMS (KS * KS)                    // float2
#define SMEM_BYTES ((SPK_ELEMS + S2P_ELEMS + SWT_ELEMS) * 8)

// Laplacian
#define LAP_ROWS (3 * LH)            // 6546
#define LAP_THREADS 256
#define LAP_VCHUNKS 958              // vector chunks: ox = 15 + 4c, c < 958
__device__ float g_partials[LAP_ROWS];

__device__ __forceinline__ int clampi(int v, int lo, int hi) {
    return min(max(v, lo), hi);
}

// ---------------------------------------------------------------------------
// Kernel 1: 25x25 depthwise blur, edge-replicate pad, + noise.
// All math as fma.rn.f32x2:
//   acc0[j] = (ch0,ch1) row y0     acc1[j] = (ch0,ch1) row y1
//   acc2[j] = (ch2 y0, ch2 y1)  via pair-packed smem s2p[r]=(in2[r],in2[r+32])
// Weights pre-duplicated in smem -> LDS.64 broadcast, no movs.
// ---------------------------------------------------------------------------
__global__ void __launch_bounds__(BLK_THREADS, 3)
blur_kernel(const float* __restrict__ img,
            const float* __restrict__ noise,
            const float* __restrict__ g,
            float* __restrict__ out)
{
    extern __shared__ float2 smem[];
    float2* spk  = smem;                       // ch0,ch1 packed   [SROWS x 57]
    float2* s2p  = spk + SPK_ELEMS;            // ch2 row pairs    [56 x 57]
    float2* swt2 = s2p + S2P_ELEMS;            // duplicated weights [625]

    const int tx0 = blockIdx.x * TILE_X;
    const int ty0 = blockIdx.y * TILE_Y;
    const int tid = threadIdx.x;

    // duplicated weights
    for (int i = tid; i < SWT_ELEMS; i += BLK_THREADS) {
        float w = g[i];
        swt2[i] = make_float2(w, w);
    }

    // ch0/ch1 tile (88 rows x 56 cols), edge clamp
    for (int i = tid; i < SROWS * SCOLS; i += BLK_THREADS) {
        int r = i / SCOLS, c = i % SCOLS;
        int gy = clampi(ty0 - PADK + r, 0, IH - 1);
        int gx = clampi(tx0 - PADK + c, 0, IW - 1);
        int gi = gy * IW + gx;
        spk[r * SSTRIDE + c] = make_float2(img[gi], img[HW + gi]);
    }

    // ch2 pair tile: s2p[r][c] = (in2[r], in2[r+32])  (56 rows x 56 cols)
    for (int i = tid; i < S2PROWS * SCOLS; i += BLK_THREADS) {
        int r = i / SCOLS, c = i % SCOLS;
        int gx  = clampi(tx0 - PADK + c, 0, IW - 1);
        int gy0 = clampi(ty0 - PADK + r,      0, IH - 1);
        int gy1 = clampi(ty0 - PADK + r + 32, 0, IH - 1);
        s2p[r * SSTRIDE + c] =
            make_float2(img[2 * HW + gy0 * IW + gx], img[2 * HW + gy1 * IW + gx]);
    }
    __syncthreads();

    const int lane = tid & 31;      // row index within tile (y0 = ty0+lane)
    const int wid  = tid >> 5;      // x-group (0..3)
    const int xb   = wid * 8;       // column base within tile

    ULL acc0[8], acc1[8], acc2[8];
#pragma unroll
    for (int j = 0; j < 8; j++) { acc0[j] = 0ull; acc1[j] = 0ull; acc2[j] = 0ull; }

#pragma unroll 1
    for (int ky = 0; ky < KS; ++ky) {
        const ULL* r0 = reinterpret_cast<const ULL*>(spk + (lane + ky) * SSTRIDE + xb);
        const ULL* r1 = reinterpret_cast<const ULL*>(spk + (lane + 32 + ky) * SSTRIDE + xb);
        const ULL* p2 = reinterpret_cast<const ULL*>(s2p + (lane + ky) * SSTRIDE + xb);
        const ULL* wp = reinterpret_cast<const ULL*>(swt2 + ky * KS);

        // prime rotating 8-wide windows
        ULL a[8], b[8], c[8];
#pragma unroll
        for (int j = 0; j < 8; j++) { a[j] = r0[j]; b[j] = r1[j]; c[j] = p2[j]; }

#pragma unroll
        for (int kx = 0; kx < KS; ++kx) {
            ULL ww = wp[kx];                       // LDS.64 uniform broadcast
#pragma unroll
            for (int j = 0; j < 8; j++) {
                const int s = (kx + j) & 7;        // rotating slot (compile-time)
                asm("fma.rn.f32x2 %0, %1, %2, %0;" : "+l"(acc0[j]) : "l"(a[s]), "l"(ww));
                asm("fma.rn.f32x2 %0, %1, %2, %0;" : "+l"(acc1[j]) : "l"(b[s]), "l"(ww));
                asm("fma.rn.f32x2 %0, %1, %2, %0;" : "+l"(acc2[j]) : "l"(c[s]), "l"(ww));
            }
            if (kx < KS - 1) {
                const int s = kx & 7;              // oldest slot -> next column
                a[s] = r0[8 + kx];
                b[s] = r1[8 + kx];
                c[s] = p2[8 + kx];
            }
        }
    }

    // stores: row y0 (always valid), row y1 = y0+32 (guard last block)
    const int x = tx0 + xb;
    {
        const int y0 = ty0 + lane;
        const int base = y0 * IW + x;
        float4 n0 = *reinterpret_cast<const float4*>(noise + base);
        float4 n1 = *reinterpret_cast<const float4*>(noise + base + 4);
        float v0[8], v1[8], v2[8];
#pragma unroll
        for (int j = 0; j < 8; j++) {
            float2 f01 = *reinterpret_cast<float2*>(&acc0[j]);
            float2 f2  = *reinterpret_cast<float2*>(&acc2[j]);
            v0[j] = f01.x; v1[j] = f01.y; v2[j] = f2.x;
        }
        *reinterpret_cast<float4*>(out + 0 * HW + base) =
            make_float4(v0[0] + n0.x, v0[1] + n0.y, v0[2] + n0.z, v0[3] + n0.w);
        *reinterpret_cast<float4*>(out + 0 * HW + base + 4) =
            make_float4(v0[4] + n1.x, v0[5] + n1.y, v0[6] + n1.z, v0[7] + n1.w);
        *reinterpret_cast<float4*>(out + 1 * HW + base) =
            make_float4(v1[0] + n0.x, v1[1] + n0.y, v1[2] + n0.z, v1[3] + n0.w);
        *reinterpret_cast<float4*>(out + 1 * HW + base + 4) =
            make_float4(v1[4] + n1.x, v1[5] + n1.y, v1[6] + n1.z, v1[7] + n1.w);
        *reinterpret_cast<float4*>(out + 2 * HW + base) =
            make_float4(v2[0] + n0.x, v2[1] + n0.y, v2[2] + n0.z, v2[3] + n0.w);
        *reinterpret_cast<float4*>(out + 2 * HW + base + 4) =
            make_float4(v2[4] + n1.x, v2[5] + n1.y, v2[6] + n1.z, v2[7] + n1.w);
    }
    const int y1 = ty0 + lane + 32;
    if (y1 < IH) {
        const int base = y1 * IW + x;
        float4 n0 = *reinterpret_cast<const float4*>(noise + base);
        float4 n1 = *reinterpret_cast<const float4*>(noise + base + 4);
        float v0[8], v1[8], v2[8];
#pragma unroll
        for (int j = 0; j < 8; j++) {
            float2 f01 = *reinterpret_cast<float2*>(&acc1[j]);
            float2 f2  = *reinterpret_cast<float2*>(&acc2[j]);
            v0[j] = f01.x; v1[j] = f01.y; v2[j] = f2.y;
        }
        *reinterpret_cast<float4*>(out + 0 * HW + base) =
            make_float4(v0[0] + n0.x, v0[1] + n0.y, v0[2] + n0.z, v0[3] + n0.w);
        *reinterpret_cast<float4*>(out + 0 * HW + base + 4) =
            make_float4(v0[4] + n1.x, v0[5] + n1.y, v0[6] + n1.z, v0[7] + n1.w);
        *reinterpret_cast<float4*>(out + 1 * HW + base) =
            make_float4(v1[0] + n0.x, v1[1] + n0.y, v1[2] + n0.z, v1[3] + n0.w);
        *reinterpret_cast<float4*>(out + 1 * HW + base + 4) =
            make_float4(v1[4] + n1.x, v1[5] + n1.y, v1[6] + n1.z, v1[7] + n1.w);
        *reinterpret_cast<float4*>(out + 2 * HW + base) =
            make_float4(v2[0] + n0.x, v2[1] + n0.y, v2[2] + n0.z, v2[3] + n0.w);
        *reinterpret_cast<float4*>(out + 2 * HW + base + 4) =
            make_float4(v2[4] + n1.x, v2[5] + n1.y, v2[6] + n1.z, v2[7] + n1.w);
    }
}

// ---------------------------------------------------------------------------
// Kernel 2: Laplacian (3x3, pad=12 replicate), squared, per-row partial sums.
// Vectorized interior (float4; 5 loads / 4 outputs), scalar clamped edges.
// ---------------------------------------------------------------------------
__global__ void __launch_bounds__(LAP_THREADS)
lap_kernel(const float* __restrict__ img)
{
    const int row = blockIdx.x;          // 0 .. LAP_ROWS-1
    const int ch  = row / LH;
    const int oy  = row - ch * LH;
    const float* p = img + ch * HW;

    const int ru = clampi(oy - 12, 0, IH - 1);
    const int rc = clampi(oy - 11, 0, IH - 1);
    const int rd = clampi(oy - 10, 0, IH - 1);
    const float* __restrict__ pu = p + ru * IW;
    const float* __restrict__ pc = p + rc * IW;
    const float* __restrict__ pd = p + rd * IW;

    float acc = 0.0f;

    // vector interior: ox = 15 + 4c, cc0 = ox-11 (16B aligned)
    for (int c = threadIdx.x; c < LAP_VCHUNKS; c += LAP_THREADS) {
        int cc0 = 4 + 4 * c;
        float4 u = *reinterpret_cast<const float4*>(pu + cc0);
        float4 m = *reinterpret_cast<const float4*>(pc + cc0);
        float4 d = *reinterpret_cast<const float4*>(pd + cc0);
        float l = pc[cc0 - 1];
        float r = pc[cc0 + 4];
        float v0 = 4.0f * m.x - u.x - d.x - l   - m.y;
        float v1 = 4.0f * m.y - u.y - d.y - m.x - m.z;
        float v2 = 4.0f * m.z - u.z - d.z - m.y - m.w;
        float v3 = 4.0f * m.w - u.w - d.w - m.z - r;
        acc = fmaf(v0, v0, acc);
        acc = fmaf(v1, v1, acc);
        acc = fmaf(v2, v2, acc);
        acc = fmaf(v3, v3, acc);
    }

    // scalar edges: ox in [0,14] and [3847, 3861]
    if (threadIdx.x < 30) {
        int t = threadIdx.x;
        int ox = (t < 15) ? t : (3832 + t);
        int cl = clampi(ox - 12, 0, IW - 1);
        int cc = clampi(ox - 11, 0, IW - 1);
        int cr = clampi(ox - 10, 0, IW - 1);
        float v = 4.0f * pc[cc] - pu[cc] - pd[cc] - pc[cl] - pc[cr];
        acc = fmaf(v, v, acc);
    }

    __shared__ float sbuf[LAP_THREADS];
    sbuf[threadIdx.x] = acc;
    __syncthreads();
#pragma unroll
    for (int s = LAP_THREADS / 2; s > 0; s >>= 1) {
        if (threadIdx.x < s) sbuf[threadIdx.x] += sbuf[threadIdx.x + s];
        __syncthreads();
    }
    if (threadIdx.x == 0) g_partials[row] = sbuf[0];
}

// ---------------------------------------------------------------------------
// Kernel 3: final deterministic reduction in double -> mean scalar.
// ---------------------------------------------------------------------------
__global__ void __launch_bounds__(256)
reduce_kernel(float* __restrict__ out_scalar)
{
    __shared__ double sd[256];
    double s = 0.0;
    for (int i = threadIdx.x; i < LAP_ROWS; i += 256) s += (double)g_partials[i];
    sd[threadIdx.x] = s;
    __syncthreads();
#pragma unroll
    for (int k = 128; k > 0; k >>= 1) {
        if (threadIdx.x < k) sd[threadIdx.x] += sd[threadIdx.x + k];
        __syncthreads();
    }
    if (threadIdx.x == 0)
        out_scalar[0] = (float)(sd[0] / (double)L3);
}

extern "C" void kernel_launch(void* const* d_in, const int* in_sizes, int n_in,
                              void* d_out, int out_size)
{
    const float* img   = (const float*)d_in[0];  // (1,3,2160,3840)
    const float* noise = (const float*)d_in[1];  // (1,1,2160,3840)
    const float* g     = (const float*)d_in[2];  // (25,25)
    float* out = (float*)d_out;                  // [3*H*W conv output, 1 scalar]

    static bool attr_set = false;
    if (!attr_set) {
        cudaFuncSetAttribute(blur_kernel,
                             cudaFuncAttributeMaxDynamicSharedMemorySize, SMEM_BYTES);
        attr_set = true;
    }

    dim3 gridB(IW / TILE_X, (IH + TILE_Y - 1) / TILE_Y);   // 120 x 34
    blur_kernel<<<gridB, BLK_THREADS, SMEM_BYTES>>>(img, noise, g, out);

    lap_kernel<<<LAP_ROWS, LAP_THREADS>>>(img);
    reduce_kernel<<<1, 256>>>(out + (out_size - 1));
}